// round 6
// baseline (speedup 1.0000x reference)
#include <cuda_runtime.h>
#include <cuda_fp16.h>
#include <math.h>

#define NN 100000
#define EE 3200000
#define HIDD 64
#define BN_EPS 1e-5f
#define NB 200          // scan blocks
#define CH 512          // elements per scan block (NB*CH = 102400 >= NN)

// ---- scratch (device globals; allocation-free) ----
__device__ int g_is64;
__device__ __align__(16) int     g_deg[NN];
__device__ __align__(16) int     g_off[NN + 1];
__device__ __align__(16) int     g_cur[NN];
__device__ __align__(16) float   g_dinv[NN];
__device__ __align__(16) int     g_csr[EE];
__device__ __align__(16) __half2 g_hsh[NN * 32];   // fp16 messages (64 dims = 32 half2)
__device__ __align__(16) float   g_act[NN * HIDD];
__device__ __align__(16) float   g_h3[NN];
__device__ __align__(16) int     g_bsum[NB];
__device__ __align__(16) int     g_bpre[NB];

// ---- zero degree counters ----
__global__ void zero_deg() {
    int i = blockIdx.x * blockDim.x + threadIdx.x;
    if (i < NN) g_deg[i] = 0;
}

// ---- detect edge_index dtype: int64 => odd 32-bit words all zero ----
__global__ void detect_kernel(const int* __restrict__ ei_w) {
    __shared__ int sor;
    if (threadIdx.x == 0) sor = 0;
    __syncthreads();
    int acc = 0;
    for (int i = threadIdx.x; i < 8192; i += blockDim.x)
        acc |= ei_w[2 * i + 1];
    if (acc) atomicOr(&sor, 1);
    __syncthreads();
    if (threadIdx.x == 0) g_is64 = (sor == 0) ? 1 : 0;
}

// ---- degree count, reading dst straight from edge_index (4 edges/thread) ----
__global__ void __launch_bounds__(256) count_kernel(const void* __restrict__ ei) {
    int i = blockIdx.x * blockDim.x + threadIdx.x;   // [0, EE/4)
    int d0, d1, d2, d3;
    if (g_is64) {
        const longlong2* p = (const longlong2*)ei + (EE / 2);  // dst block
        longlong2 a = p[2 * i], b = p[2 * i + 1];
        d0 = (int)a.x; d1 = (int)a.y; d2 = (int)b.x; d3 = (int)b.y;
    } else {
        const int4* p = (const int4*)((const int*)ei + EE);
        int4 a = p[i];
        d0 = a.x; d1 = a.y; d2 = a.z; d3 = a.w;
    }
    if ((unsigned)d0 < NN) atomicAdd(&g_deg[d0], 1);
    if ((unsigned)d1 < NN) atomicAdd(&g_deg[d1], 1);
    if ((unsigned)d2 < NN) atomicAdd(&g_deg[d2], 1);
    if ((unsigned)d3 < NN) atomicAdd(&g_deg[d3], 1);
}

// ---- scan phase A: per-block degree sums ----
__global__ void __launch_bounds__(CH) scanA() {
    int t = threadIdx.x;
    int i = blockIdx.x * CH + t;
    int d = (i < NN) ? g_deg[i] : 0;
    int lane = t & 31, w = t >> 5;
    int s = d;
#pragma unroll
    for (int o = 16; o > 0; o >>= 1) s += __shfl_xor_sync(0xffffffffu, s, o);
    __shared__ int ws[CH / 32];
    if (lane == 0) ws[w] = s;
    __syncthreads();
    if (t == 0) {
        int tot = 0;
#pragma unroll
        for (int k = 0; k < CH / 32; k++) tot += ws[k];
        g_bsum[blockIdx.x] = tot;
    }
}

// ---- scan phase B: scan the NB block sums ----
__global__ void __launch_bounds__(256) scanB() {
    __shared__ int ss[256];
    int t = threadIdx.x;
    int v = (t < NB) ? g_bsum[t] : 0;
    ss[t] = v;
    __syncthreads();
#pragma unroll
    for (int off = 1; off < 256; off <<= 1) {
        int a = (t >= off) ? ss[t - off] : 0;
        __syncthreads();
        ss[t] += a;
        __syncthreads();
    }
    if (t < NB) g_bpre[t] = ss[t] - v;
    if (t == NB - 1) g_off[NN] = ss[t];
}

// ---- scan phase C: block-local exclusive scan + off/cur/dinv ----
__global__ void __launch_bounds__(CH) scanC() {
    int t = threadIdx.x;
    int i = blockIdx.x * CH + t;
    int d = (i < NN) ? g_deg[i] : 0;
    int lane = t & 31, w = t >> 5;
    int x = d;
#pragma unroll
    for (int o = 1; o < 32; o <<= 1) {
        int y = __shfl_up_sync(0xffffffffu, x, o);
        if (lane >= o) x += y;
    }
    __shared__ int wsum[CH / 32];
    __shared__ int wpre[CH / 32];
    if (lane == 31) wsum[w] = x;
    __syncthreads();
    if (t == 0) {
        int run = 0;
#pragma unroll
        for (int k = 0; k < CH / 32; k++) { wpre[k] = run; run += wsum[k]; }
    }
    __syncthreads();
    if (i < NN) {
        int excl = g_bpre[blockIdx.x] + wpre[w] + x - d;
        g_off[i] = excl;
        g_cur[i] = excl;
        g_dinv[i] = rsqrtf((float)d + 1.0f);
    }
}

// ---- CSR fill, reading src/dst straight from edge_index (4 edges/thread) ----
__global__ void __launch_bounds__(256) fill_kernel(const void* __restrict__ ei) {
    int i = blockIdx.x * blockDim.x + threadIdx.x;   // [0, EE/4)
    int s0, s1, s2, s3, d0, d1, d2, d3;
    if (g_is64) {
        const longlong2* ps = (const longlong2*)ei;
        const longlong2* pd = ps + (EE / 2);
        longlong2 a = ps[2 * i], b = ps[2 * i + 1];
        longlong2 c = pd[2 * i], e = pd[2 * i + 1];
        s0 = (int)a.x; s1 = (int)a.y; s2 = (int)b.x; s3 = (int)b.y;
        d0 = (int)c.x; d1 = (int)c.y; d2 = (int)e.x; d3 = (int)e.y;
    } else {
        const int4* ps = (const int4*)ei;
        const int4* pd = (const int4*)((const int*)ei + EE);
        int4 a = ps[i], c = pd[i];
        s0 = a.x; s1 = a.y; s2 = a.z; s3 = a.w;
        d0 = c.x; d1 = c.y; d2 = c.z; d3 = c.w;
    }
    if ((unsigned)d0 < NN && (unsigned)s0 < NN) g_csr[atomicAdd(&g_cur[d0], 1)] = s0;
    if ((unsigned)d1 < NN && (unsigned)s1 < NN) g_csr[atomicAdd(&g_cur[d1], 1)] = s1;
    if ((unsigned)d2 < NN && (unsigned)s2 < NN) g_csr[atomicAdd(&g_cur[d2], 1)] = s2;
    if ((unsigned)d3 < NN && (unsigned)s3 < NN) g_csr[atomicAdd(&g_cur[d3], 1)] = s3;
}

// ---- GEMM: hsh[n,64] = fp16((X[n,:K] @ W[K,64]) * dinv[n]) ----
template <int K>
__global__ void __launch_bounds__(256) gemm_dinv(const float* __restrict__ X,
                                                 const float* __restrict__ W,
                                                 __half2* __restrict__ out) {
    __shared__ float Xs[64][68];
    __shared__ float Ws[64][64];
    const int t = threadIdx.x;
    const int lane = t & 31;
    const int w = t >> 5;
    const int row0 = blockIdx.x * 64;
    const int rbase = w * 8 + ((lane >> 4) << 2);  // 4 rows per thread
    const int c4 = lane & 15;

    unsigned long long acc[4][2];
#pragma unroll
    for (int j = 0; j < 4; j++) { acc[j][0] = 0ull; acc[j][1] = 0ull; }

    const int HALVES = K / 64;
    for (int h = 0; h < HALVES; h++) {
#pragma unroll
        for (int p = 0; p < 4; p++) {
            int idx = t + p * 256;
            int kk = idx >> 4, q = idx & 15;
            reinterpret_cast<float4*>(&Ws[kk][0])[q] =
                reinterpret_cast<const float4*>(W)[(size_t)(h * 64 + kk) * 16 + q];
        }
#pragma unroll
        for (int p = 0; p < 4; p++) {
            int idx = t + p * 256;
            int r = idx >> 4, q = idx & 15;
            int gr = row0 + r; if (gr >= NN) gr = NN - 1;
            reinterpret_cast<float4*>(&Xs[r][0])[q] =
                reinterpret_cast<const float4*>(X)[(size_t)gr * (K / 4) + h * 16 + q];
        }
        __syncthreads();

        unsigned wb = (unsigned)__cvta_generic_to_shared(&Ws[0][c4 * 4]);
#pragma unroll 16
        for (int kk = 0; kk < 64; kk++) {
            unsigned long long w01, w23;
            asm("ld.shared.v2.u64 {%0, %1}, [%2];"
                : "=l"(w01), "=l"(w23) : "r"(wb + kk * 256));
#pragma unroll
            for (int j = 0; j < 4; j++) {
                float xv = Xs[rbase + j][kk];
                unsigned long long xx;
                asm("mov.b64 %0, {%1, %1};" : "=l"(xx) : "f"(xv));
                asm("fma.rn.f32x2 %0, %1, %2, %3;"
                    : "=l"(acc[j][0]) : "l"(xx), "l"(w01), "l"(acc[j][0]));
                asm("fma.rn.f32x2 %0, %1, %2, %3;"
                    : "=l"(acc[j][1]) : "l"(xx), "l"(w23), "l"(acc[j][1]));
            }
        }
        __syncthreads();
    }

#pragma unroll
    for (int j = 0; j < 4; j++) {
        int r = row0 + rbase + j;
        if (r < NN) {
            float d = g_dinv[r];
            float lo, hi;
            asm("mov.b64 {%0, %1}, %2;" : "=f"(lo), "=f"(hi) : "l"(acc[j][0]));
            __half2 h01 = __float22half2_rn(make_float2(lo * d, hi * d));
            asm("mov.b64 {%0, %1}, %2;" : "=f"(lo), "=f"(hi) : "l"(acc[j][1]));
            __half2 h23 = __float22half2_rn(make_float2(lo * d, hi * d));
            uint2 packed;
            packed.x = *reinterpret_cast<unsigned*>(&h01);
            packed.y = *reinterpret_cast<unsigned*>(&h23);
            reinterpret_cast<uint2*>(out)[(size_t)r * 16 + c4] = packed;
        }
    }
}

// ---- warp-cooperative edge accumulation: coalesced index prefetch + shfl
// broadcast, hs loads batched for deep MLP. Returns fp32 accum of 2 dims/lane.
__device__ __forceinline__ float2 gather_edges(const __half2* __restrict__ hs,
                                               int node, int lane) {
    float2 acc = __half22float2(hs[(size_t)node * 32 + lane]);  // self-loop term
    int e0 = g_off[node];
    int deg = g_off[node + 1] - e0;
    for (int base = 0; base < deg; base += 32) {
        int rem = deg - base;
        int cnt = rem < 32 ? rem : 32;
        int nid = (lane < rem) ? g_csr[e0 + base + lane] : 0;
        int j = 0;
        // unrolled-by-8 batches: 8 independent gather loads in flight
        for (; j + 8 <= cnt; j += 8) {
            float2 x0 = __half22float2(hs[(size_t)__shfl_sync(0xffffffffu, nid, j + 0) * 32 + lane]);
            float2 x1 = __half22float2(hs[(size_t)__shfl_sync(0xffffffffu, nid, j + 1) * 32 + lane]);
            float2 x2 = __half22float2(hs[(size_t)__shfl_sync(0xffffffffu, nid, j + 2) * 32 + lane]);
            float2 x3 = __half22float2(hs[(size_t)__shfl_sync(0xffffffffu, nid, j + 3) * 32 + lane]);
            float2 x4 = __half22float2(hs[(size_t)__shfl_sync(0xffffffffu, nid, j + 4) * 32 + lane]);
            float2 x5 = __half22float2(hs[(size_t)__shfl_sync(0xffffffffu, nid, j + 5) * 32 + lane]);
            float2 x6 = __half22float2(hs[(size_t)__shfl_sync(0xffffffffu, nid, j + 6) * 32 + lane]);
            float2 x7 = __half22float2(hs[(size_t)__shfl_sync(0xffffffffu, nid, j + 7) * 32 + lane]);
            acc.x += x0.x + x1.x + x2.x + x3.x + x4.x + x5.x + x6.x + x7.x;
            acc.y += x0.y + x1.y + x2.y + x3.y + x4.y + x5.y + x6.y + x7.y;
        }
        for (; j < cnt; j++) {
            int s = __shfl_sync(0xffffffffu, nid, j);
            float2 xx = __half22float2(hs[(size_t)s * 32 + lane]);
            acc.x += xx.x; acc.y += xx.y;
        }
    }
    return acc;
}

// ---- gather + bias + BN + ReLU, warp per node ----
__global__ void __launch_bounds__(256) gather_bn_relu(const __half2* __restrict__ hs,
                                                      float* __restrict__ out,
                                                      const float* __restrict__ b,
                                                      const float* __restrict__ g,
                                                      const float* __restrict__ beta,
                                                      const float* __restrict__ m,
                                                      const float* __restrict__ v) {
    int warp = threadIdx.x >> 5;
    int lane = threadIdx.x & 31;
    int node = blockIdx.x * 8 + warp;
    if (node >= NN) return;

    float2 acc = gather_edges(hs, node, lane);
    float di = g_dinv[node];
    int k0 = lane * 2;
    float s0 = g[k0] * rsqrtf(v[k0] + BN_EPS);
    float s1 = g[k0 + 1] * rsqrtf(v[k0 + 1] + BN_EPS);
    float z0 = (acc.x * di + b[k0]     - m[k0])     * s0 + beta[k0];
    float z1 = (acc.y * di + b[k0 + 1] - m[k0 + 1]) * s1 + beta[k0 + 1];
    float2 o = make_float2(fmaxf(z0, 0.f), fmaxf(z1, 0.f));
    reinterpret_cast<float2*>(out)[(size_t)node * 32 + lane] = o;
}

// ---- layer-2 gather + BN + ReLU + fused W3 dot -> g_h3 ----
__global__ void __launch_bounds__(256) gather2_dot(const __half2* __restrict__ hs,
                                                   const float* __restrict__ b,
                                                   const float* __restrict__ g,
                                                   const float* __restrict__ beta,
                                                   const float* __restrict__ m,
                                                   const float* __restrict__ v,
                                                   const float* __restrict__ W3) {
    int warp = threadIdx.x >> 5;
    int lane = threadIdx.x & 31;
    int node = blockIdx.x * 8 + warp;
    if (node >= NN) return;

    float2 acc = gather_edges(hs, node, lane);
    float di = g_dinv[node];
    int k0 = lane * 2;
    float s0 = g[k0] * rsqrtf(v[k0] + BN_EPS);
    float s1 = g[k0 + 1] * rsqrtf(v[k0 + 1] + BN_EPS);
    float z0 = (acc.x * di + b[k0]     - m[k0])     * s0 + beta[k0];
    float z1 = (acc.y * di + b[k0 + 1] - m[k0 + 1]) * s1 + beta[k0 + 1];
    float o0 = fmaxf(z0, 0.f), o1 = fmaxf(z1, 0.f);

    float2 w3 = reinterpret_cast<const float2*>(W3)[lane];
    float part = o0 * w3.x + o1 * w3.y;
#pragma unroll
    for (int o = 16; o > 0; o >>= 1) part += __shfl_xor_sync(0xffffffffu, part, o);
    if (lane == 0) g_h3[node] = part * di;
}

// ---- layer-3 gather + sigmoid, warp per node ----
__global__ void __launch_bounds__(256) gather3_sigmoid(const float* __restrict__ b3,
                                                       float* __restrict__ out) {
    int warp = threadIdx.x >> 5;
    int lane = threadIdx.x & 31;
    int node = blockIdx.x * 8 + warp;
    if (node >= NN) return;
    int e0 = g_off[node], e1 = g_off[node + 1];
    float a = 0.f;
    for (int e = e0 + lane; e < e1; e += 32) a += g_h3[g_csr[e]];
#pragma unroll
    for (int o = 16; o > 0; o >>= 1) a += __shfl_xor_sync(0xffffffffu, a, o);
    if (lane == 0) {
        float z = (a + g_h3[node]) * g_dinv[node] + b3[0];
        out[node] = 1.0f / (1.0f + expf(-z));
    }
}

extern "C" void kernel_launch(void* const* d_in, const int* in_sizes, int n_in,
                              void* d_out, int out_size) {
    const float* x   = (const float*)d_in[0];
    const void*  ei  = d_in[1];
    const float* W1  = (const float*)d_in[2];
    const float* b1  = (const float*)d_in[3];
    const float* W2  = (const float*)d_in[4];
    const float* b2  = (const float*)d_in[5];
    const float* W3  = (const float*)d_in[6];
    const float* b3  = (const float*)d_in[7];
    const float* g1  = (const float*)d_in[8];
    const float* be1 = (const float*)d_in[9];
    const float* m1  = (const float*)d_in[10];
    const float* v1  = (const float*)d_in[11];
    const float* g2  = (const float*)d_in[12];
    const float* be2 = (const float*)d_in[13];
    const float* m2  = (const float*)d_in[14];
    const float* v2  = (const float*)d_in[15];

    __half2* hsh = nullptr; float* act = nullptr;
    cudaGetSymbolAddress((void**)&hsh, g_hsh);
    cudaGetSymbolAddress((void**)&act, g_act);

    zero_deg<<<(NN + 255) / 256, 256>>>();
    detect_kernel<<<1, 256>>>((const int*)ei);
    count_kernel<<<EE / 4 / 256, 256>>>(ei);
    scanA<<<NB, CH>>>();
    scanB<<<1, 256>>>();
    scanC<<<NB, CH>>>();
    fill_kernel<<<EE / 4 / 256, 256>>>(ei);

    // layer 1
    gemm_dinv<128><<<(NN + 63) / 64, 256>>>(x, W1, hsh);
    gather_bn_relu<<<NN / 8, 256>>>(hsh, act, b1, g1, be1, m1, v1);

    // layer 2 (+ fused layer-3 projection)
    gemm_dinv<64><<<(NN + 63) / 64, 256>>>(act, W2, hsh);
    gather2_dot<<<NN / 8, 256>>>(hsh, b2, g2, be2, m2, v2, W3);

    // layer 3
    gather3_sigmoid<<<NN / 8, 256>>>(b3, (float*)d_out);
}

// round 7
// speedup vs baseline: 1.0369x; 1.0369x over previous
#include <cuda_runtime.h>
#include <math.h>

#define NN 100000
#define EE 3200000
#define HIDD 64
#define BN_EPS 1e-5f
#define NB 200          // scan blocks
#define CH 512          // elements per scan block (NB*CH = 102400 >= NN)

// ---- scratch (device globals; allocation-free) ----
__device__ int g_is64;
__device__ __align__(16) int   g_deg[NN];
__device__ __align__(16) int   g_off[NN + 1];
__device__ __align__(16) int   g_cur[NN];
__device__ __align__(16) float g_dinv[NN];
__device__ __align__(16) int   g_csr[EE];
__device__ __align__(16) float g_hs[NN * HIDD];
__device__ __align__(16) float g_act[NN * HIDD];
__device__ __align__(16) float g_h3[NN];
__device__ __align__(16) int   g_bsum[NB];
__device__ __align__(16) int   g_bpre[NB];

// ---- zero degree counters ----
__global__ void zero_deg() {
    int i = blockIdx.x * blockDim.x + threadIdx.x;
    if (i < NN) g_deg[i] = 0;
}

// ---- detect edge_index dtype: int64 => odd 32-bit words all zero ----
__global__ void detect_kernel(const int* __restrict__ ei_w) {
    __shared__ int sor;
    if (threadIdx.x == 0) sor = 0;
    __syncthreads();
    int acc = 0;
    for (int i = threadIdx.x; i < 8192; i += blockDim.x)
        acc |= ei_w[2 * i + 1];
    if (acc) atomicOr(&sor, 1);
    __syncthreads();
    if (threadIdx.x == 0) g_is64 = (sor == 0) ? 1 : 0;
}

// ---- degree count, reading dst straight from edge_index (4 edges/thread) ----
__global__ void __launch_bounds__(256) count_kernel(const void* __restrict__ ei) {
    int i = blockIdx.x * blockDim.x + threadIdx.x;   // [0, EE/4)
    int d0, d1, d2, d3;
    if (g_is64) {
        const longlong2* p = (const longlong2*)ei + (EE / 2);  // dst block
        longlong2 a = p[2 * i], b = p[2 * i + 1];
        d0 = (int)a.x; d1 = (int)a.y; d2 = (int)b.x; d3 = (int)b.y;
    } else {
        const int4* p = (const int4*)((const int*)ei + EE);
        int4 a = p[i];
        d0 = a.x; d1 = a.y; d2 = a.z; d3 = a.w;
    }
    if ((unsigned)d0 < NN) atomicAdd(&g_deg[d0], 1);
    if ((unsigned)d1 < NN) atomicAdd(&g_deg[d1], 1);
    if ((unsigned)d2 < NN) atomicAdd(&g_deg[d2], 1);
    if ((unsigned)d3 < NN) atomicAdd(&g_deg[d3], 1);
}

// ---- scan phase A: per-block degree sums ----
__global__ void __launch_bounds__(CH) scanA() {
    int t = threadIdx.x;
    int i = blockIdx.x * CH + t;
    int d = (i < NN) ? g_deg[i] : 0;
    int lane = t & 31, w = t >> 5;
    int s = d;
#pragma unroll
    for (int o = 16; o > 0; o >>= 1) s += __shfl_xor_sync(0xffffffffu, s, o);
    __shared__ int ws[CH / 32];
    if (lane == 0) ws[w] = s;
    __syncthreads();
    if (t == 0) {
        int tot = 0;
#pragma unroll
        for (int k = 0; k < CH / 32; k++) tot += ws[k];
        g_bsum[blockIdx.x] = tot;
    }
}

// ---- scan phase B: scan the NB block sums ----
__global__ void __launch_bounds__(256) scanB() {
    __shared__ int ss[256];
    int t = threadIdx.x;
    int v = (t < NB) ? g_bsum[t] : 0;
    ss[t] = v;
    __syncthreads();
#pragma unroll
    for (int off = 1; off < 256; off <<= 1) {
        int a = (t >= off) ? ss[t - off] : 0;
        __syncthreads();
        ss[t] += a;
        __syncthreads();
    }
    if (t < NB) g_bpre[t] = ss[t] - v;
    if (t == NB - 1) g_off[NN] = ss[t];
}

// ---- scan phase C: block-local exclusive scan + off/cur/dinv ----
__global__ void __launch_bounds__(CH) scanC() {
    int t = threadIdx.x;
    int i = blockIdx.x * CH + t;
    int d = (i < NN) ? g_deg[i] : 0;
    int lane = t & 31, w = t >> 5;
    int x = d;
#pragma unroll
    for (int o = 1; o < 32; o <<= 1) {
        int y = __shfl_up_sync(0xffffffffu, x, o);
        if (lane >= o) x += y;
    }
    __shared__ int wsum[CH / 32];
    __shared__ int wpre[CH / 32];
    if (lane == 31) wsum[w] = x;
    __syncthreads();
    if (t == 0) {
        int run = 0;
#pragma unroll
        for (int k = 0; k < CH / 32; k++) { wpre[k] = run; run += wsum[k]; }
    }
    __syncthreads();
    if (i < NN) {
        int excl = g_bpre[blockIdx.x] + wpre[w] + x - d;
        g_off[i] = excl;
        g_cur[i] = excl;
        g_dinv[i] = rsqrtf((float)d + 1.0f);
    }
}

// ---- CSR fill, reading src/dst straight from edge_index (4 edges/thread) ----
__global__ void __launch_bounds__(256) fill_kernel(const void* __restrict__ ei) {
    int i = blockIdx.x * blockDim.x + threadIdx.x;   // [0, EE/4)
    int s0, s1, s2, s3, d0, d1, d2, d3;
    if (g_is64) {
        const longlong2* ps = (const longlong2*)ei;
        const longlong2* pd = ps + (EE / 2);
        longlong2 a = ps[2 * i], b = ps[2 * i + 1];
        longlong2 c = pd[2 * i], e = pd[2 * i + 1];
        s0 = (int)a.x; s1 = (int)a.y; s2 = (int)b.x; s3 = (int)b.y;
        d0 = (int)c.x; d1 = (int)c.y; d2 = (int)e.x; d3 = (int)e.y;
    } else {
        const int4* ps = (const int4*)ei;
        const int4* pd = (const int4*)((const int*)ei + EE);
        int4 a = ps[i], c = pd[i];
        s0 = a.x; s1 = a.y; s2 = a.z; s3 = a.w;
        d0 = c.x; d1 = c.y; d2 = c.z; d3 = c.w;
    }
    if ((unsigned)d0 < NN && (unsigned)s0 < NN) g_csr[atomicAdd(&g_cur[d0], 1)] = s0;
    if ((unsigned)d1 < NN && (unsigned)s1 < NN) g_csr[atomicAdd(&g_cur[d1], 1)] = s1;
    if ((unsigned)d2 < NN && (unsigned)s2 < NN) g_csr[atomicAdd(&g_cur[d2], 1)] = s2;
    if ((unsigned)d3 < NN && (unsigned)s3 < NN) g_csr[atomicAdd(&g_cur[d3], 1)] = s3;
}

// ---- GEMM: hs[n,64] = (X[n,:K] @ W[K,64]) * dinv[n]  (fp32 out) ----
template <int K>
__global__ void __launch_bounds__(256) gemm_dinv(const float* __restrict__ X,
                                                 const float* __restrict__ W,
                                                 float* __restrict__ out) {
    __shared__ float Xs[64][68];
    __shared__ float Ws[64][64];
    const int t = threadIdx.x;
    const int lane = t & 31;
    const int w = t >> 5;
    const int row0 = blockIdx.x * 64;
    const int rbase = w * 8 + ((lane >> 4) << 2);  // 4 rows per thread
    const int c4 = lane & 15;

    unsigned long long acc[4][2];
#pragma unroll
    for (int j = 0; j < 4; j++) { acc[j][0] = 0ull; acc[j][1] = 0ull; }

    const int HALVES = K / 64;
    for (int h = 0; h < HALVES; h++) {
#pragma unroll
        for (int p = 0; p < 4; p++) {
            int idx = t + p * 256;
            int kk = idx >> 4, q = idx & 15;
            reinterpret_cast<float4*>(&Ws[kk][0])[q] =
                reinterpret_cast<const float4*>(W)[(size_t)(h * 64 + kk) * 16 + q];
        }
#pragma unroll
        for (int p = 0; p < 4; p++) {
            int idx = t + p * 256;
            int r = idx >> 4, q = idx & 15;
            int gr = row0 + r; if (gr >= NN) gr = NN - 1;
            reinterpret_cast<float4*>(&Xs[r][0])[q] =
                reinterpret_cast<const float4*>(X)[(size_t)gr * (K / 4) + h * 16 + q];
        }
        __syncthreads();

        unsigned wb = (unsigned)__cvta_generic_to_shared(&Ws[0][c4 * 4]);
#pragma unroll 16
        for (int kk = 0; kk < 64; kk++) {
            unsigned long long w01, w23;
            asm("ld.shared.v2.u64 {%0, %1}, [%2];"
                : "=l"(w01), "=l"(w23) : "r"(wb + kk * 256));
#pragma unroll
            for (int j = 0; j < 4; j++) {
                float xv = Xs[rbase + j][kk];
                unsigned long long xx;
                asm("mov.b64 %0, {%1, %1};" : "=l"(xx) : "f"(xv));
                asm("fma.rn.f32x2 %0, %1, %2, %3;"
                    : "=l"(acc[j][0]) : "l"(xx), "l"(w01), "l"(acc[j][0]));
                asm("fma.rn.f32x2 %0, %1, %2, %3;"
                    : "=l"(acc[j][1]) : "l"(xx), "l"(w23), "l"(acc[j][1]));
            }
        }
        __syncthreads();
    }

#pragma unroll
    for (int j = 0; j < 4; j++) {
        int r = row0 + rbase + j;
        if (r < NN) {
            float d = g_dinv[r];
            float lo, hi;
            float4 o;
            asm("mov.b64 {%0, %1}, %2;" : "=f"(lo), "=f"(hi) : "l"(acc[j][0]));
            o.x = lo * d; o.y = hi * d;
            asm("mov.b64 {%0, %1}, %2;" : "=f"(lo), "=f"(hi) : "l"(acc[j][1]));
            o.z = lo * d; o.w = hi * d;
            reinterpret_cast<float4*>(out)[(size_t)r * 16 + c4] = o;
        }
    }
}

// ---- edge-vectorized gather: 2 edges per warp-round, float4 per lane.
// Self-loop folded in as virtual edge p==deg. Result: acc[4] for dims
// (lane&15)*4 .. +4, valid in ALL lanes after the xor-16 reduction.
__device__ __forceinline__ void gather_vec(const float4* __restrict__ hs4,
                                           int node, int lane, float acc[4]) {
    const int sub = lane >> 4;        // edge slot 0/1
    const int c4 = lane & 15;         // float4 column within row
    int e0 = g_off[node];
    int deg = g_off[node + 1] - e0;
    int total = deg + 1;              // + self-loop
    acc[0] = acc[1] = acc[2] = acc[3] = 0.f;

#pragma unroll 4
    for (int base = 0; base < total; base += 2) {
        int p = base + sub;
        int q = (p < deg) ? p : 0;
        int addr = e0 + q; if (addr >= EE) addr = EE - 1;
        int nid = g_csr[addr];
        if (p >= deg) nid = node;     // p==deg: self; p>deg: masked below
        float4 r = hs4[(size_t)nid * 16 + c4];
        if (p < total) {
            acc[0] += r.x; acc[1] += r.y; acc[2] += r.z; acc[3] += r.w;
        }
    }
#pragma unroll
    for (int k = 0; k < 4; k++)
        acc[k] += __shfl_xor_sync(0xffffffffu, acc[k], 16);
}

// ---- gather + bias + BN + ReLU, warp per node ----
__global__ void __launch_bounds__(256) gather_bn_relu(const float* __restrict__ hs,
                                                      float* __restrict__ out,
                                                      const float* __restrict__ b,
                                                      const float* __restrict__ g,
                                                      const float* __restrict__ beta,
                                                      const float* __restrict__ m,
                                                      const float* __restrict__ v) {
    int warp = threadIdx.x >> 5;
    int lane = threadIdx.x & 31;
    int node = blockIdx.x * 8 + warp;
    if (node >= NN) return;

    float acc[4];
    gather_vec(reinterpret_cast<const float4*>(hs), node, lane, acc);

    int c4 = lane & 15;
    if (lane < 16) {
        float di = g_dinv[node];
        float4 bb = reinterpret_cast<const float4*>(b)[c4];
        float4 gg = reinterpret_cast<const float4*>(g)[c4];
        float4 be = reinterpret_cast<const float4*>(beta)[c4];
        float4 mm = reinterpret_cast<const float4*>(m)[c4];
        float4 vv = reinterpret_cast<const float4*>(v)[c4];
        float4 o;
        o.x = fmaxf((acc[0] * di + bb.x - mm.x) * (gg.x * rsqrtf(vv.x + BN_EPS)) + be.x, 0.f);
        o.y = fmaxf((acc[1] * di + bb.y - mm.y) * (gg.y * rsqrtf(vv.y + BN_EPS)) + be.y, 0.f);
        o.z = fmaxf((acc[2] * di + bb.z - mm.z) * (gg.z * rsqrtf(vv.z + BN_EPS)) + be.z, 0.f);
        o.w = fmaxf((acc[3] * di + bb.w - mm.w) * (gg.w * rsqrtf(vv.w + BN_EPS)) + be.w, 0.f);
        reinterpret_cast<float4*>(out)[(size_t)node * 16 + c4] = o;
    }
}

// ---- layer-2 gather + BN + ReLU + fused W3 dot -> g_h3 ----
__global__ void __launch_bounds__(256) gather2_dot(const float* __restrict__ hs,
                                                   const float* __restrict__ b,
                                                   const float* __restrict__ g,
                                                   const float* __restrict__ beta,
                                                   const float* __restrict__ m,
                                                   const float* __restrict__ v,
                                                   const float* __restrict__ W3) {
    int warp = threadIdx.x >> 5;
    int lane = threadIdx.x & 31;
    int node = blockIdx.x * 8 + warp;
    if (node >= NN) return;

    float acc[4];
    gather_vec(reinterpret_cast<const float4*>(hs), node, lane, acc);

    int c4 = lane & 15;
    float di = g_dinv[node];
    float4 bb = reinterpret_cast<const float4*>(b)[c4];
    float4 gg = reinterpret_cast<const float4*>(g)[c4];
    float4 be = reinterpret_cast<const float4*>(beta)[c4];
    float4 mm = reinterpret_cast<const float4*>(m)[c4];
    float4 vv = reinterpret_cast<const float4*>(v)[c4];
    float o0 = fmaxf((acc[0] * di + bb.x - mm.x) * (gg.x * rsqrtf(vv.x + BN_EPS)) + be.x, 0.f);
    float o1 = fmaxf((acc[1] * di + bb.y - mm.y) * (gg.y * rsqrtf(vv.y + BN_EPS)) + be.y, 0.f);
    float o2 = fmaxf((acc[2] * di + bb.z - mm.z) * (gg.z * rsqrtf(vv.z + BN_EPS)) + be.z, 0.f);
    float o3 = fmaxf((acc[3] * di + bb.w - mm.w) * (gg.w * rsqrtf(vv.w + BN_EPS)) + be.w, 0.f);

    float4 w3 = reinterpret_cast<const float4*>(W3)[c4];
    float part = o0 * w3.x + o1 * w3.y + o2 * w3.z + o3 * w3.w;
#pragma unroll
    for (int o = 8; o > 0; o >>= 1) part += __shfl_xor_sync(0xffffffffu, part, o);
    if (lane == 0) g_h3[node] = part * di;
}

// ---- layer-3 gather + sigmoid, warp per node ----
__global__ void __launch_bounds__(256) gather3_sigmoid(const float* __restrict__ b3,
                                                       float* __restrict__ out) {
    int warp = threadIdx.x >> 5;
    int lane = threadIdx.x & 31;
    int node = blockIdx.x * 8 + warp;
    if (node >= NN) return;
    int e0 = g_off[node], e1 = g_off[node + 1];
    float a = 0.f;
    for (int e = e0 + lane; e < e1; e += 32) a += g_h3[g_csr[e]];
#pragma unroll
    for (int o = 16; o > 0; o >>= 1) a += __shfl_xor_sync(0xffffffffu, a, o);
    if (lane == 0) {
        float z = (a + g_h3[node]) * g_dinv[node] + b3[0];
        out[node] = 1.0f / (1.0f + expf(-z));
    }
}

extern "C" void kernel_launch(void* const* d_in, const int* in_sizes, int n_in,
                              void* d_out, int out_size) {
    const float* x   = (const float*)d_in[0];
    const void*  ei  = d_in[1];
    const float* W1  = (const float*)d_in[2];
    const float* b1  = (const float*)d_in[3];
    const float* W2  = (const float*)d_in[4];
    const float* b2  = (const float*)d_in[5];
    const float* W3  = (const float*)d_in[6];
    const float* b3  = (const float*)d_in[7];
    const float* g1  = (const float*)d_in[8];
    const float* be1 = (const float*)d_in[9];
    const float* m1  = (const float*)d_in[10];
    const float* v1  = (const float*)d_in[11];
    const float* g2  = (const float*)d_in[12];
    const float* be2 = (const float*)d_in[13];
    const float* m2  = (const float*)d_in[14];
    const float* v2  = (const float*)d_in[15];

    float *hs = nullptr, *act = nullptr;
    cudaGetSymbolAddress((void**)&hs, g_hs);
    cudaGetSymbolAddress((void**)&act, g_act);

    zero_deg<<<(NN + 255) / 256, 256>>>();
    detect_kernel<<<1, 256>>>((const int*)ei);
    count_kernel<<<EE / 4 / 256, 256>>>(ei);
    scanA<<<NB, CH>>>();
    scanB<<<1, 256>>>();
    scanC<<<NB, CH>>>();
    fill_kernel<<<EE / 4 / 256, 256>>>(ei);

    // layer 1
    gemm_dinv<128><<<(NN + 63) / 64, 256>>>(x, W1, hs);
    gather_bn_relu<<<NN / 8, 256>>>(hs, act, b1, g1, be1, m1, v1);

    // layer 2 (+ fused layer-3 projection)
    gemm_dinv<64><<<(NN + 63) / 64, 256>>>(act, W2, hs);
    gather2_dot<<<NN / 8, 256>>>(hs, b2, g2, be2, m2, v2, W3);

    // layer 3
    gather3_sigmoid<<<NN / 8, 256>>>(b3, (float*)d_out);
}